// round 1
// baseline (speedup 1.0000x reference)
#include <cuda_runtime.h>

#define DIMN 128
#define NB   16384
#define EPSL 1e-6f
#define L2E  1.4426950408889634f

// ---- scratch (static device globals; no allocation) ----
__device__ float  g_ps[NB * DIMN];   // p_star[nodes_p_star]
__device__ float  g_pp[NB * DIMN];   // p[nodes_p]
__device__ float  g_ns[NB];          // |ps row|^2
__device__ float  g_np[NB];          // |pp row|^2
__device__ float  g_bs[NB];          // beta_p_star[nodes_p_star]
__device__ float  g_bp[NB];          // beta_p[nodes_p]
__device__ double g_acc[2];          // [0]=link, [1]=nonlink

static __device__ __forceinline__ float sqrt_approx(float x) {
    float r; asm("sqrt.approx.f32 %0, %1;" : "=f"(r) : "f"(x)); return r;
}
static __device__ __forceinline__ float ex2_approx(float x) {
    float r; asm("ex2.approx.f32 %0, %1;" : "=f"(r) : "f"(x)); return r;
}

__global__ void k_zero() { g_acc[0] = 0.0; g_acc[1] = 0.0; }

// One warp per row: gather ps/pp rows, row norms, betas.
__global__ void k_gather(const int* __restrict__ nps, const int* __restrict__ npp,
                         const float* __restrict__ beta_p, const float* __restrict__ beta_ps,
                         const float* __restrict__ p, const float* __restrict__ pstar) {
    int row  = blockIdx.x * 8 + (threadIdx.x >> 5);
    int lane = threadIdx.x & 31;
    if (row >= NB) return;
    int is = nps[row], ip = npp[row];
    float4 vs = ((const float4*)(pstar + (size_t)is * DIMN))[lane];
    float4 vp = ((const float4*)(p     + (size_t)ip * DIMN))[lane];
    ((float4*)(g_ps + (size_t)row * DIMN))[lane] = vs;
    ((float4*)(g_pp + (size_t)row * DIMN))[lane] = vp;
    float a = vs.x*vs.x + vs.y*vs.y + vs.z*vs.z + vs.w*vs.w;
    float b = vp.x*vp.x + vp.y*vp.y + vp.z*vp.z + vp.w*vp.w;
#pragma unroll
    for (int o = 16; o; o >>= 1) {
        a += __shfl_xor_sync(0xffffffffu, a, o);
        b += __shfl_xor_sync(0xffffffffu, b, o);
    }
    if (lane == 0) {
        g_ns[row] = a; g_np[row] = b;
        g_bs[row] = beta_ps[is]; g_bp[row] = beta_p[ip];
    }
}

// Link term: one warp per edge (grid-stride).
// sum over edges of (beta_p_star[e0] + beta_p[e1] - ||p[e0] - p_star[e1] + eps||)
__global__ void k_link(const int* __restrict__ edges, int E,
                       const float* __restrict__ beta_p, const float* __restrict__ beta_ps,
                       const float* __restrict__ p, const float* __restrict__ pstar) {
    int gw   = (blockIdx.x * blockDim.x + threadIdx.x) >> 5;
    int lane = threadIdx.x & 31;
    int nw   = (gridDim.x * blockDim.x) >> 5;
    float local = 0.f;
    for (int e = gw; e < E; e += nw) {
        int e0 = edges[e], e1 = edges[E + e];
        float4 a = ((const float4*)(p     + (size_t)e0 * DIMN))[lane];
        float4 b = ((const float4*)(pstar + (size_t)e1 * DIMN))[lane];
        float dx = a.x - b.x + EPSL, dy = a.y - b.y + EPSL;
        float dz = a.z - b.z + EPSL, dw = a.w - b.w + EPSL;
        float s = dx*dx + dy*dy + dz*dz + dw*dw;
#pragma unroll
        for (int o = 16; o; o >>= 1) s += __shfl_xor_sync(0xffffffffu, s, o);
        if (lane == 0) local += beta_ps[e0] + beta_p[e1] - sqrt_approx(s);
    }
    if (lane == 0) atomicAdd(&g_acc[0], (double)local);
}

// Non-link: triu-only tiled fused GEMM + epilogue.
// Tile 128x128, 256 threads, 8x8 per thread, packed f32x2 FMA accumulators.
// A stored element-duplicated in smem so both MMA operands are natural f32x2 pairs.
#define BMT 128
#define BNT 128
#define BKT 16

__global__ __launch_bounds__(256, 2) void k_nonlink() {
    int bx = blockIdx.x, by = blockIdx.y;
    if (bx < by) return;  // tile fully below the strict upper triangle

    __shared__ float As2[BKT][2 * BMT + 4];  // duplicated A rows (ps)
    __shared__ float Bs[BKT][BNT + 4];       // B rows (pp)
    __shared__ float warpsum[8];

    int tid = threadIdx.x;
    int tx = tid & 15, ty = tid >> 4;
    int row0 = by * BMT, col0 = bx * BNT;

    unsigned long long acc[8][4];
#pragma unroll
    for (int i = 0; i < 8; i++)
#pragma unroll
        for (int j = 0; j < 4; j++) acc[i][j] = 0ull;

    for (int kk = 0; kk < DIMN; kk += BKT) {
#pragma unroll
        for (int it = 0; it < 2; it++) {
            int idx = tid + it * 256;
            int m  = idx >> 2;
            int k4 = (idx & 3) << 2;
            const float4 av = *(const float4*)&g_ps[(size_t)(row0 + m) * DIMN + kk + k4];
            const float4 bv = *(const float4*)&g_pp[(size_t)(col0 + m) * DIMN + kk + k4];
            As2[k4 + 0][2*m] = av.x; As2[k4 + 0][2*m + 1] = av.x;
            As2[k4 + 1][2*m] = av.y; As2[k4 + 1][2*m + 1] = av.y;
            As2[k4 + 2][2*m] = av.z; As2[k4 + 2][2*m + 1] = av.z;
            As2[k4 + 3][2*m] = av.w; As2[k4 + 3][2*m + 1] = av.w;
            Bs[k4 + 0][m] = bv.x; Bs[k4 + 1][m] = bv.y;
            Bs[k4 + 2][m] = bv.z; Bs[k4 + 3][m] = bv.w;
        }
        __syncthreads();
#pragma unroll
        for (int k = 0; k < BKT; k++) {
            unsigned long long a2[8], b2[4];
#pragma unroll
            for (int ii = 0; ii < 4; ii++) {
                ulonglong2 q = *(const ulonglong2*)&As2[k][ty * 16 + ii * 4];
                a2[2*ii] = q.x; a2[2*ii + 1] = q.y;
            }
#pragma unroll
            for (int jj = 0; jj < 2; jj++) {
                ulonglong2 q = *(const ulonglong2*)&Bs[k][tx * 8 + jj * 4];
                b2[2*jj] = q.x; b2[2*jj + 1] = q.y;
            }
#pragma unroll
            for (int i = 0; i < 8; i++)
#pragma unroll
                for (int j = 0; j < 4; j++)
                    asm("fma.rn.f32x2 %0, %1, %2, %0;"
                        : "+l"(acc[i][j]) : "l"(a2[i]), "l"(b2[j]));
        }
        __syncthreads();
    }

    // Epilogue: sq = |s|^2 + |m|^2 - 2 g; dist = sqrt(max(sq,0));
    // w = exp(bs + bp - dist) if s < m.
    int sb = row0 + ty * 8, cb = col0 + tx * 8;
    float nsr[8], bsr[8], npc[8], bpc[8];
#pragma unroll
    for (int i = 0; i < 8; i++) { nsr[i] = g_ns[sb + i]; bsr[i] = g_bs[sb + i]; }
#pragma unroll
    for (int j = 0; j < 8; j++) { npc[j] = g_np[cb + j]; bpc[j] = g_bp[cb + j]; }

    float lsum = 0.f;
#pragma unroll
    for (int i = 0; i < 8; i++) {
#pragma unroll
        for (int jj = 0; jj < 4; jj++) {
#pragma unroll
            for (int h = 0; h < 2; h++) {
                unsigned u = (h == 0) ? (unsigned)acc[i][jj]
                                      : (unsigned)(acc[i][jj] >> 32);
                float g = __uint_as_float(u);
                int j = jj * 2 + h;
                float sq = fmaxf(nsr[i] + npc[j] - 2.f * g, 0.f);
                float dist = sqrt_approx(sq);
                float w = ex2_approx((bsr[i] + bpc[j] - dist) * L2E);
                if (sb + i < cb + j) lsum += w;
            }
        }
    }
#pragma unroll
    for (int o = 16; o; o >>= 1) lsum += __shfl_xor_sync(0xffffffffu, lsum, o);
    if ((tid & 31) == 0) warpsum[tid >> 5] = lsum;
    __syncthreads();
    if (tid == 0) {
        float s = 0.f;
#pragma unroll
        for (int w = 0; w < 8; w++) s += warpsum[w];
        atomicAdd(&g_acc[1], (double)s);
    }
}

__global__ void k_final(float* out) {
    out[0] = (float)(g_acc[1] - g_acc[0]);   // -(link - nonlink)
}

extern "C" void kernel_launch(void* const* d_in, const int* in_sizes, int n_in,
                              void* d_out, int out_size) {
    const int*   edges   = (const int*)d_in[0];
    const int*   nps     = (const int*)d_in[1];   // nodes_p_star
    const int*   npp     = (const int*)d_in[2];   // nodes_p
    const float* beta_p  = (const float*)d_in[3];
    const float* beta_ps = (const float*)d_in[4];
    const float* p       = (const float*)d_in[5];
    const float* pstar   = (const float*)d_in[6];
    float* out = (float*)d_out;
    int E = in_sizes[0] / 2;

    k_zero<<<1, 1>>>();
    k_gather<<<NB / 8, 256>>>(nps, npp, beta_p, beta_ps, p, pstar);
    k_link<<<2048, 256>>>(edges, E, beta_p, beta_ps, p, pstar);
    k_nonlink<<<dim3(NB / BNT, NB / BMT), 256>>>();
    k_final<<<1, 1>>>(out);
}

// round 3
// speedup vs baseline: 2.7582x; 2.7582x over previous
#include <cuda_runtime.h>
#include <cuda_bf16.h>
#include <cstdint>

#define DIMN 128
#define NB   16384
#define NT   (NB / 128)                 // 128 tile rows/cols
#define NTILES (NT * (NT + 1) / 2)      // 8256 triu tiles
#define EPSL 1e-6f
#define L2E  1.4426950408889634f
#define GRID_NL 148

// smem tile geometry: 128 rows x 128 bf16, padded to 136 bf16 (272 B) per row
#define ROWB 272
#define TILEB (128 * ROWB)              // 34816 B per operand tile
#define STAGEB (2 * TILEB)              // A + B per stage
#define DYN_SMEM (2 * STAGEB)           // 2 stages = 139264 B

// ---- scratch (static device globals; no allocation) ----
__device__ __align__(16) __nv_bfloat16 g_ps_bf[NB * DIMN];  // p_star[nodes_p_star]
__device__ __align__(16) __nv_bfloat16 g_pp_bf[NB * DIMN];  // p[nodes_p]
__device__ float  g_ns[NB];
__device__ float  g_np[NB];
__device__ float  g_bs[NB];
__device__ float  g_bp[NB];
__device__ double g_acc[2];          // [0]=link, [1]=nonlink

static __device__ __forceinline__ float sqrt_approx(float x) {
    float r; asm("sqrt.approx.f32 %0, %1;" : "=f"(r) : "f"(x)); return r;
}
static __device__ __forceinline__ float ex2_approx(float x) {
    float r; asm("ex2.approx.f32 %0, %1;" : "=f"(r) : "f"(x)); return r;
}
static __device__ __forceinline__ uint32_t smem_u32(const void* p) {
    uint32_t a;
    asm("{ .reg .u64 t; cvta.to.shared.u64 t, %1; cvt.u32.u64 %0, t; }" : "=r"(a) : "l"(p));
    return a;
}
static __device__ __forceinline__ void cp_async16(uint32_t dst, const void* src) {
    asm volatile("cp.async.cg.shared.global [%0], [%1], 16;" :: "r"(dst), "l"(src) : "memory");
}
static __device__ __forceinline__ void cp_commit() {
    asm volatile("cp.async.commit_group;" ::: "memory");
}
template <int N> static __device__ __forceinline__ void cp_wait() {
    asm volatile("cp.async.wait_group %0;" :: "n"(N) : "memory");
}
static __device__ __forceinline__ void ldsm_x4(uint32_t& r0, uint32_t& r1,
                                               uint32_t& r2, uint32_t& r3, uint32_t a) {
    asm volatile("ldmatrix.sync.aligned.m8n8.x4.shared.b16 {%0,%1,%2,%3}, [%4];"
                 : "=r"(r0), "=r"(r1), "=r"(r2), "=r"(r3) : "r"(a));
}
static __device__ __forceinline__ void mma16816(float* d, const uint32_t* a,
                                                uint32_t b0, uint32_t b1) {
    asm volatile("mma.sync.aligned.m16n8k16.row.col.f32.bf16.bf16.f32 "
                 "{%0,%1,%2,%3}, {%4,%5,%6,%7}, {%8,%9}, {%0,%1,%2,%3};"
                 : "+f"(d[0]), "+f"(d[1]), "+f"(d[2]), "+f"(d[3])
                 : "r"(a[0]), "r"(a[1]), "r"(a[2]), "r"(a[3]), "r"(b0), "r"(b1));
}

// ---------------- kernels ----------------
__global__ void k_zero() { g_acc[0] = 0.0; g_acc[1] = 0.0; }

// One warp per row: gather bf16 rows, fp32 row norms, betas.
__global__ void k_gather(const int* __restrict__ nps, const int* __restrict__ npp,
                         const float* __restrict__ beta_p, const float* __restrict__ beta_ps,
                         const float* __restrict__ p, const float* __restrict__ pstar) {
    int row  = blockIdx.x * 8 + (threadIdx.x >> 5);
    int lane = threadIdx.x & 31;
    if (row >= NB) return;
    int is = nps[row], ip = npp[row];
    float4 vs = ((const float4*)(pstar + (size_t)is * DIMN))[lane];
    float4 vp = ((const float4*)(p     + (size_t)ip * DIMN))[lane];
    __nv_bfloat162* ds = (__nv_bfloat162*)(g_ps_bf + (size_t)row * DIMN);
    __nv_bfloat162* dp = (__nv_bfloat162*)(g_pp_bf + (size_t)row * DIMN);
    ds[2 * lane + 0] = __floats2bfloat162_rn(vs.x, vs.y);
    ds[2 * lane + 1] = __floats2bfloat162_rn(vs.z, vs.w);
    dp[2 * lane + 0] = __floats2bfloat162_rn(vp.x, vp.y);
    dp[2 * lane + 1] = __floats2bfloat162_rn(vp.z, vp.w);
    float a = vs.x*vs.x + vs.y*vs.y + vs.z*vs.z + vs.w*vs.w;
    float b = vp.x*vp.x + vp.y*vp.y + vp.z*vp.z + vp.w*vp.w;
#pragma unroll
    for (int o = 16; o; o >>= 1) {
        a += __shfl_xor_sync(0xffffffffu, a, o);
        b += __shfl_xor_sync(0xffffffffu, b, o);
    }
    if (lane == 0) {
        g_ns[row] = a; g_np[row] = b;
        g_bs[row] = beta_ps[is]; g_bp[row] = beta_p[ip];
    }
}

// Link term: one warp per edge (grid-stride).
__global__ void k_link(const int* __restrict__ edges, int E,
                       const float* __restrict__ beta_p, const float* __restrict__ beta_ps,
                       const float* __restrict__ p, const float* __restrict__ pstar) {
    int gw   = (blockIdx.x * blockDim.x + threadIdx.x) >> 5;
    int lane = threadIdx.x & 31;
    int nw   = (gridDim.x * blockDim.x) >> 5;
    float local = 0.f;
    for (int e = gw; e < E; e += nw) {
        int e0 = edges[e], e1 = edges[E + e];
        float4 a = ((const float4*)(p     + (size_t)e0 * DIMN))[lane];
        float4 b = ((const float4*)(pstar + (size_t)e1 * DIMN))[lane];
        float dx = a.x - b.x + EPSL, dy = a.y - b.y + EPSL;
        float dz = a.z - b.z + EPSL, dw = a.w - b.w + EPSL;
        float s = dx*dx + dy*dy + dz*dz + dw*dw;
#pragma unroll
        for (int o = 16; o; o >>= 1) s += __shfl_xor_sync(0xffffffffu, s, o);
        if (lane == 0) local += beta_ps[e0] + beta_p[e1] - sqrt_approx(s);
    }
    if (lane == 0) atomicAdd(&g_acc[0], (double)local);
}

// Non-link: persistent mma.sync bf16 GEMM over triu 128x128 tiles + fused epilogue.
// 8 warps, each computes a 32x64 strip. 2-stage cp.async pipeline across tiles.
__global__ __launch_bounds__(256, 1)
void k_nonlink_mma() {
    extern __shared__ __align__(16) char smem[];
    const int tid  = threadIdx.x;
    const int wid  = tid >> 5;
    const int lane = tid & 31;
    const uint32_t sbase = smem_u32(smem);

    const int wm = wid & 3;           // 4 M-strips of 32
    const int wn = wid >> 2;          // 2 N-strips of 64
    const int row0w = wm * 32;
    const int col0w = wn * 64;

    // decode helper state
    float nls = 0.f;

    // ldmatrix per-lane base offsets (within an operand tile)
    const uint32_t lm_off = (uint32_t)(lane & 15) * ROWB + (uint32_t)(lane >> 4) * 16;

    // --- prologue: load tile t0 into stage 0 ---
    int t = blockIdx.x;
    {
        // decode t -> (by, bx)
        int by = (int)(((2.0 * NT + 1.0) -
                        sqrt((2.0 * NT + 1.0) * (2.0 * NT + 1.0) - 8.0 * (double)t)) * 0.5);
        while ((by + 1) * NT - ((by + 1) * by) / 2 <= t) by++;
        while (by * NT - (by * (by - 1)) / 2 > t) by--;
        const int bx = by + (t - (by * NT - (by * (by - 1)) / 2));
        const int row0 = by << 7, col0 = bx << 7;
        const uint32_t a0 = sbase;            // stage 0 A
        const uint32_t b0 = sbase + TILEB;    // stage 0 B
#pragma unroll
        for (int it = 0; it < 8; it++) {
            const int c = tid + (it << 8);    // 0..2047
            const int m = c >> 4, q = c & 15;
            cp_async16(a0 + (uint32_t)m * ROWB + (uint32_t)q * 16,
                       (const char*)g_ps_bf + ((size_t)(row0 + m) << 8) + ((size_t)q << 4));
            cp_async16(b0 + (uint32_t)m * ROWB + (uint32_t)q * 16,
                       (const char*)g_pp_bf + ((size_t)(col0 + m) << 8) + ((size_t)q << 4));
        }
        cp_commit();
    }

    int s = 0;
    for (; t < NTILES; t += GRID_NL) {
        // decode current tile coords (again; cheap vs tile work)
        int by = (int)(((2.0 * NT + 1.0) -
                        sqrt((2.0 * NT + 1.0) * (2.0 * NT + 1.0) - 8.0 * (double)t)) * 0.5);
        while ((by + 1) * NT - ((by + 1) * by) / 2 <= t) by++;
        while (by * NT - (by * (by - 1)) / 2 > t) by--;
        const int bx = by + (t - (by * NT - (by * (by - 1)) / 2));
        const int row0 = by << 7, col0 = bx << 7;

        // issue next tile's loads into the other stage
        const int tn = t + GRID_NL;
        if (tn < NTILES) {
            int by2 = (int)(((2.0 * NT + 1.0) -
                             sqrt((2.0 * NT + 1.0) * (2.0 * NT + 1.0) - 8.0 * (double)tn)) * 0.5);
            while ((by2 + 1) * NT - ((by2 + 1) * by2) / 2 <= tn) by2++;
            while (by2 * NT - (by2 * (by2 - 1)) / 2 > tn) by2--;
            const int bx2 = by2 + (tn - (by2 * NT - (by2 * (by2 - 1)) / 2));
            const int r2 = by2 << 7, c2 = bx2 << 7;
            const uint32_t an = sbase + (uint32_t)(1 - s) * STAGEB;
            const uint32_t bn = an + TILEB;
#pragma unroll
            for (int it = 0; it < 8; it++) {
                const int c = tid + (it << 8);
                const int m = c >> 4, q = c & 15;
                cp_async16(an + (uint32_t)m * ROWB + (uint32_t)q * 16,
                           (const char*)g_ps_bf + ((size_t)(r2 + m) << 8) + ((size_t)q << 4));
                cp_async16(bn + (uint32_t)m * ROWB + (uint32_t)q * 16,
                           (const char*)g_pp_bf + ((size_t)(c2 + m) << 8) + ((size_t)q << 4));
            }
        }
        cp_commit();
        cp_wait<1>();          // current tile's data resident
        __syncthreads();

        const uint32_t abase = sbase + (uint32_t)s * STAGEB;
        const uint32_t bbase = abase + TILEB;
        const uint32_t aw = abase + (uint32_t)row0w * ROWB + lm_off;
        const uint32_t bw = bbase + (uint32_t)col0w * ROWB + lm_off;

        float acc[2][8][4];
#pragma unroll
        for (int mi = 0; mi < 2; mi++)
#pragma unroll
            for (int ni = 0; ni < 8; ni++)
#pragma unroll
                for (int v = 0; v < 4; v++) acc[mi][ni][v] = 0.f;

#pragma unroll
        for (int k = 0; k < 8; k++) {
            uint32_t a[2][4], bf[4][4];
#pragma unroll
            for (int mi = 0; mi < 2; mi++)
                ldsm_x4(a[mi][0], a[mi][1], a[mi][2], a[mi][3],
                        aw + (uint32_t)mi * 16 * ROWB + (uint32_t)k * 32);
#pragma unroll
            for (int nj = 0; nj < 4; nj++)
                ldsm_x4(bf[nj][0], bf[nj][1], bf[nj][2], bf[nj][3],
                        bw + (uint32_t)nj * 16 * ROWB + (uint32_t)k * 32);
#pragma unroll
            for (int mi = 0; mi < 2; mi++)
#pragma unroll
                for (int ni = 0; ni < 8; ni++) {
                    const int nj = ni >> 1;
                    if ((ni & 1) == 0) mma16816(acc[mi][ni], a[mi], bf[nj][0], bf[nj][2]);
                    else               mma16816(acc[mi][ni], a[mi], bf[nj][1], bf[nj][3]);
                }
        }

        // fused epilogue
        const int rbase = row0 + row0w + (lane >> 2);
        const int cbase = col0 + col0w + 2 * (lane & 3);
#pragma unroll
        for (int mi = 0; mi < 2; mi++) {
            const int r_lo = rbase + mi * 16;
            const float ns0 = __ldg(&g_ns[r_lo]),     bs0 = __ldg(&g_bs[r_lo]);
            const float ns1 = __ldg(&g_ns[r_lo + 8]), bs1 = __ldg(&g_bs[r_lo + 8]);
#pragma unroll
            for (int ni = 0; ni < 8; ni++) {
                const int c0 = cbase + ni * 8;
                const float np0 = __ldg(&g_np[c0]),     bp0 = __ldg(&g_bp[c0]);
                const float np1 = __ldg(&g_np[c0 + 1]), bp1 = __ldg(&g_bp[c0 + 1]);
                const float* d = acc[mi][ni];

                float sq, w;
                sq = fmaxf(ns0 + np0 - 2.f * d[0], 0.f);
                w  = ex2_approx((bs0 + bp0 - sqrt_approx(sq)) * L2E);
                if (r_lo < c0) nls += w;
                sq = fmaxf(ns0 + np1 - 2.f * d[1], 0.f);
                w  = ex2_approx((bs0 + bp1 - sqrt_approx(sq)) * L2E);
                if (r_lo < c0 + 1) nls += w;
                sq = fmaxf(ns1 + np0 - 2.f * d[2], 0.f);
                w  = ex2_approx((bs1 + bp0 - sqrt_approx(sq)) * L2E);
                if (r_lo + 8 < c0) nls += w;
                sq = fmaxf(ns1 + np1 - 2.f * d[3], 0.f);
                w  = ex2_approx((bs1 + bp1 - sqrt_approx(sq)) * L2E);
                if (r_lo + 8 < c0 + 1) nls += w;
            }
        }
        __syncthreads();   // strip done before next iter overwrites this stage
        s ^= 1;
    }

#pragma unroll
    for (int o = 16; o; o >>= 1) nls += __shfl_xor_sync(0xffffffffu, nls, o);
    if (lane == 0) atomicAdd(&g_acc[1], (double)nls);
}

__global__ void k_final(float* out) {
    out[0] = (float)(g_acc[1] - g_acc[0]);   // -(link - nonlink)
}

extern "C" void kernel_launch(void* const* d_in, const int* in_sizes, int n_in,
                              void* d_out, int out_size) {
    const int*   edges   = (const int*)d_in[0];
    const int*   nps     = (const int*)d_in[1];   // nodes_p_star
    const int*   npp     = (const int*)d_in[2];   // nodes_p
    const float* beta_p  = (const float*)d_in[3];
    const float* beta_ps = (const float*)d_in[4];
    const float* p       = (const float*)d_in[5];
    const float* pstar   = (const float*)d_in[6];
    float* out = (float*)d_out;
    int E = in_sizes[0] / 2;

    cudaFuncSetAttribute(k_nonlink_mma, cudaFuncAttributeMaxDynamicSharedMemorySize, DYN_SMEM);

    k_zero<<<1, 1>>>();
    k_gather<<<NB / 8, 256>>>(nps, npp, beta_p, beta_ps, p, pstar);
    k_link<<<2048, 256>>>(edges, E, beta_p, beta_ps, p, pstar);
    k_nonlink_mma<<<GRID_NL, 256, DYN_SMEM>>>();
    k_final<<<1, 1>>>(out);
}

// round 4
// speedup vs baseline: 3.8938x; 1.4117x over previous
#include <cuda_runtime.h>
#include <cuda_bf16.h>
#include <cstdint>

#define DIMN 128
#define NB   16384
#define NN   20000
#define NT   (NB / 128)                 // 128 tile rows/cols
#define NTILES (NT * (NT + 1) / 2)      // 8256 triu tiles
#define EPSL 1e-6f
#define L2E  1.4426950408889634f
#define GRID_NL 148

// smem tile geometry: 128 rows x 128 bf16, padded to 136 bf16 (272 B) per row
#define ROWB 272
#define TILEB (128 * ROWB)              // 34816 B per operand tile
#define STAGEB (2 * TILEB)              // A + B per stage
#define DYN_SMEM (2 * STAGEB)           // 2 stages = 139264 B

// ---- scratch (static device globals; no allocation) ----
__device__ __align__(16) __nv_bfloat16 g_p_bf[NN * DIMN];     // full p table, bf16
__device__ __align__(16) __nv_bfloat16 g_pstar_bf[NN * DIMN]; // full p_star table, bf16
__device__ __align__(16) __nv_bfloat16 g_ps_bf[NB * DIMN];    // L2E * p_star[nodes_p_star]
__device__ __align__(16) __nv_bfloat16 g_pp_bf[NB * DIMN];    // L2E * p[nodes_p]
__device__ float    g_ns[NB];          // |scaled ps row|^2
__device__ float    g_np[NB];          // |scaled pp row|^2
__device__ float    g_bs[NB];          // L2E * beta_p_star[nodes_p_star]
__device__ float    g_bp[NB];          // L2E * beta_p[nodes_p]
__device__ uint32_t g_tile[NTILES];    // by<<16 | bx
__device__ double   g_acc[2];          // [0]=link, [1]=nonlink

static __device__ __forceinline__ float sqrt_approx(float x) {
    float r; asm("sqrt.approx.f32 %0, %1;" : "=f"(r) : "f"(x)); return r;
}
static __device__ __forceinline__ float ex2_approx(float x) {
    float r; asm("ex2.approx.f32 %0, %1;" : "=f"(r) : "f"(x)); return r;
}
static __device__ __forceinline__ uint32_t smem_u32(const void* p) {
    uint32_t a;
    asm("{ .reg .u64 t; cvta.to.shared.u64 t, %1; cvt.u32.u64 %0, t; }" : "=r"(a) : "l"(p));
    return a;
}
static __device__ __forceinline__ void cp_async16(uint32_t dst, const void* src) {
    asm volatile("cp.async.cg.shared.global [%0], [%1], 16;" :: "r"(dst), "l"(src) : "memory");
}
static __device__ __forceinline__ void cp_commit() {
    asm volatile("cp.async.commit_group;" ::: "memory");
}
template <int N> static __device__ __forceinline__ void cp_wait() {
    asm volatile("cp.async.wait_group %0;" :: "n"(N) : "memory");
}
static __device__ __forceinline__ void ldsm_x4(uint32_t& r0, uint32_t& r1,
                                               uint32_t& r2, uint32_t& r3, uint32_t a) {
    asm volatile("ldmatrix.sync.aligned.m8n8.x4.shared.b16 {%0,%1,%2,%3}, [%4];"
                 : "=r"(r0), "=r"(r1), "=r"(r2), "=r"(r3) : "r"(a));
}
static __device__ __forceinline__ void mma16816(float* d, const uint32_t* a,
                                                uint32_t b0, uint32_t b1) {
    asm volatile("mma.sync.aligned.m16n8k16.row.col.f32.bf16.bf16.f32 "
                 "{%0,%1,%2,%3}, {%4,%5,%6,%7}, {%8,%9}, {%0,%1,%2,%3};"
                 : "+f"(d[0]), "+f"(d[1]), "+f"(d[2]), "+f"(d[3])
                 : "r"(a[0]), "r"(a[1]), "r"(a[2]), "r"(a[3]), "r"(b0), "r"(b1));
}
static __device__ __forceinline__ float2 bf2f(uint32_t u) {
    __nv_bfloat162 h = *reinterpret_cast<__nv_bfloat162*>(&u);
    return __bfloat1622float2(h);
}

// ---------------- kernels ----------------
// zero accumulators + build triu tile map
__global__ void k_init() {
    int t = blockIdx.x * 256 + threadIdx.x;
    if (t == 0) { g_acc[0] = 0.0; g_acc[1] = 0.0; }
    if (t >= NTILES) return;
    float A = 2.f * NT + 1.f;
    int by = (int)((A - sqrtf(A * A - 8.f * (float)t)) * 0.5f);
    if (by < 0) by = 0;
    if (by > NT - 1) by = NT - 1;
    while ((by + 1) * NT - ((by + 1) * by) / 2 <= t) by++;
    while (by * NT - (by * (by - 1)) / 2 > t) by--;
    int bx = by + (t - (by * NT - (by * (by - 1)) / 2));
    g_tile[t] = ((uint32_t)by << 16) | (uint32_t)bx;
}

// convert full p / p_star tables to bf16 (one warp per row per table)
__global__ void k_prep(const float* __restrict__ p, const float* __restrict__ pstar) {
    int w    = blockIdx.x * 8 + (threadIdx.x >> 5);
    int lane = threadIdx.x & 31;
    int row  = w >> 1;
    if (row >= NN) return;
    const float* src = (w & 1) ? pstar : p;
    __nv_bfloat16* dst = (w & 1) ? g_pstar_bf : g_p_bf;
    float4 v = ((const float4*)(src + (size_t)row * DIMN))[lane];
    __nv_bfloat162* d = (__nv_bfloat162*)(dst + (size_t)row * DIMN);
    d[2 * lane + 0] = __floats2bfloat162_rn(v.x, v.y);
    d[2 * lane + 1] = __floats2bfloat162_rn(v.z, v.w);
}

// gather rows (from bf16 tables), scale by L2E, store scaled bf16 + norms + scaled betas
__global__ void k_gather(const int* __restrict__ nps, const int* __restrict__ npp,
                         const float* __restrict__ beta_p, const float* __restrict__ beta_ps) {
    int row  = blockIdx.x * 8 + (threadIdx.x >> 5);
    int lane = threadIdx.x & 31;
    if (row >= NB) return;
    int is = nps[row], ip = npp[row];
    uint2 rs = ((const uint2*)(g_pstar_bf + (size_t)is * DIMN))[lane];
    uint2 rp = ((const uint2*)(g_p_bf     + (size_t)ip * DIMN))[lane];

    float2 s0 = bf2f(rs.x), s1 = bf2f(rs.y), p0 = bf2f(rp.x), p1 = bf2f(rp.y);
    __nv_bfloat162 os0 = __floats2bfloat162_rn(s0.x * L2E, s0.y * L2E);
    __nv_bfloat162 os1 = __floats2bfloat162_rn(s1.x * L2E, s1.y * L2E);
    __nv_bfloat162 op0 = __floats2bfloat162_rn(p0.x * L2E, p0.y * L2E);
    __nv_bfloat162 op1 = __floats2bfloat162_rn(p1.x * L2E, p1.y * L2E);
    ((__nv_bfloat162*)(g_ps_bf + (size_t)row * DIMN))[2 * lane + 0] = os0;
    ((__nv_bfloat162*)(g_ps_bf + (size_t)row * DIMN))[2 * lane + 1] = os1;
    ((__nv_bfloat162*)(g_pp_bf + (size_t)row * DIMN))[2 * lane + 0] = op0;
    ((__nv_bfloat162*)(g_pp_bf + (size_t)row * DIMN))[2 * lane + 1] = op1;

    float2 a0 = __bfloat1622float2(os0), a1 = __bfloat1622float2(os1);
    float2 b0 = __bfloat1622float2(op0), b1 = __bfloat1622float2(op1);
    float a = a0.x*a0.x + a0.y*a0.y + a1.x*a1.x + a1.y*a1.y;
    float b = b0.x*b0.x + b0.y*b0.y + b1.x*b1.x + b1.y*b1.y;
#pragma unroll
    for (int o = 16; o; o >>= 1) {
        a += __shfl_xor_sync(0xffffffffu, a, o);
        b += __shfl_xor_sync(0xffffffffu, b, o);
    }
    if (lane == 0) {
        g_ns[row] = a; g_np[row] = b;
        g_bs[row] = beta_ps[is] * L2E; g_bp[row] = beta_p[ip] * L2E;
    }
}

// Link term: one warp per edge, bf16 rows (halved traffic), block-level reduce.
__global__ void k_link(const int* __restrict__ edges, int E,
                       const float* __restrict__ beta_p, const float* __restrict__ beta_ps) {
    __shared__ float wsum[8];
    int gw   = (blockIdx.x * blockDim.x + threadIdx.x) >> 5;
    int wid  = threadIdx.x >> 5;
    int lane = threadIdx.x & 31;
    int nw   = (gridDim.x * blockDim.x) >> 5;
    float local = 0.f;
    for (int e = gw; e < E; e += nw) {
        int e0 = edges[e], e1 = edges[E + e];
        uint2 ra = ((const uint2*)(g_p_bf     + (size_t)e0 * DIMN))[lane];
        uint2 rb = ((const uint2*)(g_pstar_bf + (size_t)e1 * DIMN))[lane];
        float2 a0 = bf2f(ra.x), a1 = bf2f(ra.y);
        float2 b0 = bf2f(rb.x), b1 = bf2f(rb.y);
        float d0 = a0.x - b0.x + EPSL, d1 = a0.y - b0.y + EPSL;
        float d2 = a1.x - b1.x + EPSL, d3 = a1.y - b1.y + EPSL;
        float s = d0*d0 + d1*d1 + d2*d2 + d3*d3;
#pragma unroll
        for (int o = 16; o; o >>= 1) s += __shfl_xor_sync(0xffffffffu, s, o);
        if (lane == 0) local += beta_ps[e0] + beta_p[e1] - sqrt_approx(s);
    }
    if (lane == 0) wsum[wid] = local;
    __syncthreads();
    if (threadIdx.x == 0) {
        float s = 0.f;
#pragma unroll
        for (int w = 0; w < 8; w++) s += wsum[w];
        atomicAdd(&g_acc[0], (double)s);
    }
}

// Non-link: persistent mma.sync bf16 GEMM over triu 128x128 tiles + fused epilogue.
// 16 warps, each a 32x32 strip. 2-stage cp.async pipeline across tiles.
__global__ __launch_bounds__(512, 1)
void k_nonlink_mma() {
    extern __shared__ __align__(16) char smem[];
    __shared__ float warpsum[16];
    const int tid  = threadIdx.x;
    const int wid  = tid >> 5;
    const int lane = tid & 31;
    const uint32_t sbase = smem_u32(smem);

    const int row0w = (wid & 3) * 32;     // 4 M-strips of 32
    const int col0w = (wid >> 2) * 32;    // 4 N-strips of 32

    float nls = 0.f;
    const uint32_t lm_off = (uint32_t)(lane & 15) * ROWB + (uint32_t)(lane >> 4) * 16;

    // --- prologue: load tile t0 into stage 0 ---
    int t = blockIdx.x;
    {
        const uint32_t tc = g_tile[t];
        const int row0 = (int)(tc >> 16) << 7, col0 = (int)(tc & 0xffffu) << 7;
        const uint32_t a0 = sbase, b0 = sbase + TILEB;
#pragma unroll
        for (int it = 0; it < 4; it++) {
            const int c = tid + (it << 9);
            const int m = c >> 4, q = c & 15;
            cp_async16(a0 + (uint32_t)m * ROWB + (uint32_t)q * 16,
                       (const char*)g_ps_bf + ((size_t)(row0 + m) << 8) + ((size_t)q << 4));
            cp_async16(b0 + (uint32_t)m * ROWB + (uint32_t)q * 16,
                       (const char*)g_pp_bf + ((size_t)(col0 + m) << 8) + ((size_t)q << 4));
        }
        cp_commit();
    }

    int s = 0;
    for (; t < NTILES; t += GRID_NL) {
        const uint32_t tc = g_tile[t];
        const int by = (int)(tc >> 16), bx = (int)(tc & 0xffffu);
        const int row0 = by << 7, col0 = bx << 7;

        // prefetch next tile into other stage
        const int tn = t + GRID_NL;
        if (tn < NTILES) {
            const uint32_t tc2 = g_tile[tn];
            const int r2 = (int)(tc2 >> 16) << 7, c2 = (int)(tc2 & 0xffffu) << 7;
            const uint32_t an = sbase + (uint32_t)(1 - s) * STAGEB;
            const uint32_t bn = an + TILEB;
#pragma unroll
            for (int it = 0; it < 4; it++) {
                const int c = tid + (it << 9);
                const int m = c >> 4, q = c & 15;
                cp_async16(an + (uint32_t)m * ROWB + (uint32_t)q * 16,
                           (const char*)g_ps_bf + ((size_t)(r2 + m) << 8) + ((size_t)q << 4));
                cp_async16(bn + (uint32_t)m * ROWB + (uint32_t)q * 16,
                           (const char*)g_pp_bf + ((size_t)(c2 + m) << 8) + ((size_t)q << 4));
            }
        }
        cp_commit();
        cp_wait<1>();
        __syncthreads();

        const uint32_t abase = sbase + (uint32_t)s * STAGEB;
        const uint32_t bbase = abase + TILEB;
        const uint32_t aw = abase + (uint32_t)row0w * ROWB + lm_off;
        const uint32_t bw = bbase + (uint32_t)col0w * ROWB + lm_off;

        float acc[2][4][4];
#pragma unroll
        for (int mi = 0; mi < 2; mi++)
#pragma unroll
            for (int ni = 0; ni < 4; ni++)
#pragma unroll
                for (int v = 0; v < 4; v++) acc[mi][ni][v] = 0.f;

#pragma unroll
        for (int k = 0; k < 8; k++) {
            uint32_t a[2][4], bf[2][4];
#pragma unroll
            for (int mi = 0; mi < 2; mi++)
                ldsm_x4(a[mi][0], a[mi][1], a[mi][2], a[mi][3],
                        aw + (uint32_t)mi * 16 * ROWB + (uint32_t)k * 32);
#pragma unroll
            for (int nj = 0; nj < 2; nj++)
                ldsm_x4(bf[nj][0], bf[nj][1], bf[nj][2], bf[nj][3],
                        bw + (uint32_t)nj * 16 * ROWB + (uint32_t)k * 32);
#pragma unroll
            for (int mi = 0; mi < 2; mi++)
#pragma unroll
                for (int ni = 0; ni < 4; ni++) {
                    const int nj = ni >> 1;
                    if ((ni & 1) == 0) mma16816(acc[mi][ni], a[mi], bf[nj][0], bf[nj][2]);
                    else               mma16816(acc[mi][ni], a[mi], bf[nj][1], bf[nj][3]);
                }
        }

        // fused epilogue (all values pre-scaled by L2E; w = ex2(bsum - sqrt(nsum - 2g)))
        const int rbase = row0 + row0w + (lane >> 2);
        const int cbase = col0 + col0w + 2 * (lane & 3);
        if (bx != by) {
            // strictly above diagonal: every element counts
#pragma unroll
            for (int mi = 0; mi < 2; mi++) {
                const int r_lo = rbase + mi * 16;
                const float ns0 = __ldg(&g_ns[r_lo]),     bs0 = __ldg(&g_bs[r_lo]);
                const float ns1 = __ldg(&g_ns[r_lo + 8]), bs1 = __ldg(&g_bs[r_lo + 8]);
#pragma unroll
                for (int ni = 0; ni < 4; ni++) {
                    const int c0 = cbase + ni * 8;
                    const float np0 = __ldg(&g_np[c0]),     bp0 = __ldg(&g_bp[c0]);
                    const float np1 = __ldg(&g_np[c0 + 1]), bp1 = __ldg(&g_bp[c0 + 1]);
                    const float* d = acc[mi][ni];
                    nls += ex2_approx(bs0 + bp0 - sqrt_approx(fmaxf(ns0 + np0 - 2.f * d[0], 0.f)));
                    nls += ex2_approx(bs0 + bp1 - sqrt_approx(fmaxf(ns0 + np1 - 2.f * d[1], 0.f)));
                    nls += ex2_approx(bs1 + bp0 - sqrt_approx(fmaxf(ns1 + np0 - 2.f * d[2], 0.f)));
                    nls += ex2_approx(bs1 + bp1 - sqrt_approx(fmaxf(ns1 + np1 - 2.f * d[3], 0.f)));
                }
            }
        } else {
#pragma unroll
            for (int mi = 0; mi < 2; mi++) {
                const int r_lo = rbase + mi * 16;
                const float ns0 = __ldg(&g_ns[r_lo]),     bs0 = __ldg(&g_bs[r_lo]);
                const float ns1 = __ldg(&g_ns[r_lo + 8]), bs1 = __ldg(&g_bs[r_lo + 8]);
#pragma unroll
                for (int ni = 0; ni < 4; ni++) {
                    const int c0 = cbase + ni * 8;
                    const float np0 = __ldg(&g_np[c0]),     bp0 = __ldg(&g_bp[c0]);
                    const float np1 = __ldg(&g_np[c0 + 1]), bp1 = __ldg(&g_bp[c0 + 1]);
                    const float* d = acc[mi][ni];
                    float w;
                    w = ex2_approx(bs0 + bp0 - sqrt_approx(fmaxf(ns0 + np0 - 2.f * d[0], 0.f)));
                    if (r_lo < c0) nls += w;
                    w = ex2_approx(bs0 + bp1 - sqrt_approx(fmaxf(ns0 + np1 - 2.f * d[1], 0.f)));
                    if (r_lo < c0 + 1) nls += w;
                    w = ex2_approx(bs1 + bp0 - sqrt_approx(fmaxf(ns1 + np0 - 2.f * d[2], 0.f)));
                    if (r_lo + 8 < c0) nls += w;
                    w = ex2_approx(bs1 + bp1 - sqrt_approx(fmaxf(ns1 + np1 - 2.f * d[3], 0.f)));
                    if (r_lo + 8 < c0 + 1) nls += w;
                }
            }
        }
        __syncthreads();   // all warps done reading stage s before next prefetch overwrites it
        s ^= 1;
    }

#pragma unroll
    for (int o = 16; o; o >>= 1) nls += __shfl_xor_sync(0xffffffffu, nls, o);
    if (lane == 0) warpsum[wid] = nls;
    __syncthreads();
    if (tid == 0) {
        float sum = 0.f;
#pragma unroll
        for (int w = 0; w < 16; w++) sum += warpsum[w];
        atomicAdd(&g_acc[1], (double)sum);
    }
}

__global__ void k_final(float* out) {
    out[0] = (float)(g_acc[1] - g_acc[0]);   // -(link - nonlink)
}

extern "C" void kernel_launch(void* const* d_in, const int* in_sizes, int n_in,
                              void* d_out, int out_size) {
    const int*   edges   = (const int*)d_in[0];
    const int*   nps     = (const int*)d_in[1];   // nodes_p_star
    const int*   npp     = (const int*)d_in[2];   // nodes_p
    const float* beta_p  = (const float*)d_in[3];
    const float* beta_ps = (const float*)d_in[4];
    const float* p       = (const float*)d_in[5];
    const float* pstar   = (const float*)d_in[6];
    float* out = (float*)d_out;
    int E = in_sizes[0] / 2;

    cudaFuncSetAttribute(k_nonlink_mma, cudaFuncAttributeMaxDynamicSharedMemorySize, DYN_SMEM);

    k_init<<<(NTILES + 255) / 256, 256>>>();
    k_prep<<<(2 * NN + 7) / 8, 256>>>(p, pstar);
    k_gather<<<NB / 8, 256>>>(nps, npp, beta_p, beta_ps);
    k_link<<<2048, 256>>>(edges, E, beta_p, beta_ps);
    k_nonlink_mma<<<GRID_NL, 512, DYN_SMEM>>>();
    k_final<<<1, 1>>>(out);
}

// round 5
// speedup vs baseline: 4.7937x; 1.2311x over previous
#include <cuda_runtime.h>
#include <cuda_bf16.h>
#include <cstdint>

#define DIMN 128
#define NB   16384
#define NN   20000
#define NT   (NB / 128)                 // 128 tile rows/cols
#define NTILES (NT * (NT + 1) / 2)      // 8256 triu tiles
#define EPSL 1e-6f
#define L2E  1.4426950408889634f
#define GRID_NL 296                     // 2 CTAs per SM

// smem tile geometry: 128 rows x 128 bf16, padded to 136 bf16 (272 B) per row
#define ROWB 272
#define TILEB (128 * ROWB)              // 34816 B per operand tile
#define DYN_SMEM_NL (2 * TILEB)         // single stage: A + B = 69632 B

// ---- scratch (static device globals; no allocation) ----
__device__ __align__(16) __nv_bfloat16 g_p_bf[NN * DIMN];     // full p table, bf16
__device__ __align__(16) __nv_bfloat16 g_pstar_bf[NN * DIMN]; // full p_star table, bf16
__device__ __align__(16) __nv_bfloat16 g_ps_bf[NB * DIMN];    // L2E * p_star[nodes_p_star]
__device__ __align__(16) __nv_bfloat16 g_pp_bf[NB * DIMN];    // L2E * p[nodes_p]
__device__ float    g_ns[NB];          // |scaled ps row|^2
__device__ float    g_np[NB];          // |scaled pp row|^2
__device__ float    g_bs[NB];          // L2E * beta_p_star[nodes_p_star]
__device__ float    g_bp[NB];          // L2E * beta_p[nodes_p]
__device__ uint32_t g_tile[NTILES];    // by<<16 | bx
__device__ double   g_acc[2];          // [0]=link, [1]=nonlink

static __device__ __forceinline__ float sqrt_approx(float x) {
    float r; asm("sqrt.approx.f32 %0, %1;" : "=f"(r) : "f"(x)); return r;
}
static __device__ __forceinline__ float ex2_approx(float x) {
    float r; asm("ex2.approx.f32 %0, %1;" : "=f"(r) : "f"(x)); return r;
}
static __device__ __forceinline__ uint32_t smem_u32(const void* p) {
    uint32_t a;
    asm("{ .reg .u64 t; cvta.to.shared.u64 t, %1; cvt.u32.u64 %0, t; }" : "=r"(a) : "l"(p));
    return a;
}
static __device__ __forceinline__ void cp_async16(uint32_t dst, const void* src) {
    asm volatile("cp.async.cg.shared.global [%0], [%1], 16;" :: "r"(dst), "l"(src) : "memory");
}
static __device__ __forceinline__ void cp_commit() {
    asm volatile("cp.async.commit_group;" ::: "memory");
}
template <int N> static __device__ __forceinline__ void cp_wait() {
    asm volatile("cp.async.wait_group %0;" :: "n"(N) : "memory");
}
static __device__ __forceinline__ void ldsm_x4(uint32_t& r0, uint32_t& r1,
                                               uint32_t& r2, uint32_t& r3, uint32_t a) {
    asm volatile("ldmatrix.sync.aligned.m8n8.x4.shared.b16 {%0,%1,%2,%3}, [%4];"
                 : "=r"(r0), "=r"(r1), "=r"(r2), "=r"(r3) : "r"(a));
}
static __device__ __forceinline__ void mma16816(float* d, const uint32_t* a,
                                                uint32_t b0, uint32_t b1) {
    asm volatile("mma.sync.aligned.m16n8k16.row.col.f32.bf16.bf16.f32 "
                 "{%0,%1,%2,%3}, {%4,%5,%6,%7}, {%8,%9}, {%0,%1,%2,%3};"
                 : "+f"(d[0]), "+f"(d[1]), "+f"(d[2]), "+f"(d[3])
                 : "r"(a[0]), "r"(a[1]), "r"(a[2]), "r"(a[3]), "r"(b0), "r"(b1));
}
static __device__ __forceinline__ float2 bf2f(uint32_t u) {
    __nv_bfloat162 h = *reinterpret_cast<__nv_bfloat162*>(&u);
    return __bfloat1622float2(h);
}

// ---------------- kernels ----------------
// zero accumulators + build triu tile map
__global__ void k_init() {
    int t = blockIdx.x * 256 + threadIdx.x;
    if (t == 0) { g_acc[0] = 0.0; g_acc[1] = 0.0; }
    if (t >= NTILES) return;
    float A = 2.f * NT + 1.f;
    int by = (int)((A - sqrtf(A * A - 8.f * (float)t)) * 0.5f);
    if (by < 0) by = 0;
    if (by > NT - 1) by = NT - 1;
    while ((by + 1) * NT - ((by + 1) * by) / 2 <= t) by++;
    while (by * NT - (by * (by - 1)) / 2 > t) by--;
    int bx = by + (t - (by * NT - (by * (by - 1)) / 2));
    g_tile[t] = ((uint32_t)by << 16) | (uint32_t)bx;
}

// convert full p / p_star tables to bf16 (one warp per row per table)
__global__ void k_prep(const float* __restrict__ p, const float* __restrict__ pstar) {
    int w    = blockIdx.x * 8 + (threadIdx.x >> 5);
    int lane = threadIdx.x & 31;
    int row  = w >> 1;
    if (row >= NN) return;
    const float* src = (w & 1) ? pstar : p;
    __nv_bfloat16* dst = (w & 1) ? g_pstar_bf : g_p_bf;
    float4 v = ((const float4*)(src + (size_t)row * DIMN))[lane];
    __nv_bfloat162* d = (__nv_bfloat162*)(dst + (size_t)row * DIMN);
    d[2 * lane + 0] = __floats2bfloat162_rn(v.x, v.y);
    d[2 * lane + 1] = __floats2bfloat162_rn(v.z, v.w);
}

// gather rows (from bf16 tables), scale by L2E, store scaled bf16 + norms + scaled betas
__global__ void k_gather(const int* __restrict__ nps, const int* __restrict__ npp,
                         const float* __restrict__ beta_p, const float* __restrict__ beta_ps) {
    int row  = blockIdx.x * 8 + (threadIdx.x >> 5);
    int lane = threadIdx.x & 31;
    if (row >= NB) return;
    int is = nps[row], ip = npp[row];
    uint2 rs = ((const uint2*)(g_pstar_bf + (size_t)is * DIMN))[lane];
    uint2 rp = ((const uint2*)(g_p_bf     + (size_t)ip * DIMN))[lane];

    float2 s0 = bf2f(rs.x), s1 = bf2f(rs.y), p0 = bf2f(rp.x), p1 = bf2f(rp.y);
    __nv_bfloat162 os0 = __floats2bfloat162_rn(s0.x * L2E, s0.y * L2E);
    __nv_bfloat162 os1 = __floats2bfloat162_rn(s1.x * L2E, s1.y * L2E);
    __nv_bfloat162 op0 = __floats2bfloat162_rn(p0.x * L2E, p0.y * L2E);
    __nv_bfloat162 op1 = __floats2bfloat162_rn(p1.x * L2E, p1.y * L2E);
    ((__nv_bfloat162*)(g_ps_bf + (size_t)row * DIMN))[2 * lane + 0] = os0;
    ((__nv_bfloat162*)(g_ps_bf + (size_t)row * DIMN))[2 * lane + 1] = os1;
    ((__nv_bfloat162*)(g_pp_bf + (size_t)row * DIMN))[2 * lane + 0] = op0;
    ((__nv_bfloat162*)(g_pp_bf + (size_t)row * DIMN))[2 * lane + 1] = op1;

    float2 a0 = __bfloat1622float2(os0), a1 = __bfloat1622float2(os1);
    float2 b0 = __bfloat1622float2(op0), b1 = __bfloat1622float2(op1);
    float a = a0.x*a0.x + a0.y*a0.y + a1.x*a1.x + a1.y*a1.y;
    float b = b0.x*b0.x + b0.y*b0.y + b1.x*b1.x + b1.y*b1.y;
#pragma unroll
    for (int o = 16; o; o >>= 1) {
        a += __shfl_xor_sync(0xffffffffu, a, o);
        b += __shfl_xor_sync(0xffffffffu, b, o);
    }
    if (lane == 0) {
        g_ns[row] = a; g_np[row] = b;
        g_bs[row] = beta_ps[is] * L2E; g_bp[row] = beta_p[ip] * L2E;
    }
}

// Link term: 8 lanes per edge, 4 edges per warp in parallel (3-deep shfl reduce).
__global__ void k_link(const int* __restrict__ edges, int E,
                       const float* __restrict__ beta_p, const float* __restrict__ beta_ps) {
    __shared__ float wsum[8];
    const int gw   = (blockIdx.x * blockDim.x + threadIdx.x) >> 5;
    const int wid  = threadIdx.x >> 5;
    const int lane = threadIdx.x & 31;
    const int nw   = (gridDim.x * blockDim.x) >> 5;
    const int sub  = lane & 7;     // lane within 8-lane edge group
    const int eq   = lane >> 3;    // which of 4 edges this group handles

    float local = 0.f;
    for (int base = gw * 4; base < E; base += nw * 4) {
        const int e = base + eq;
        const bool valid = (e < E);
        float s = 0.f;
        int e0 = 0, e1 = 0;
        if (valid) {
            e0 = edges[e]; e1 = edges[E + e];
            const uint4* ra = (const uint4*)(g_p_bf     + (size_t)e0 * DIMN);
            const uint4* rb = (const uint4*)(g_pstar_bf + (size_t)e1 * DIMN);
            const uint4 a0 = ra[2 * sub], a1 = ra[2 * sub + 1];
            const uint4 b0 = rb[2 * sub], b1 = rb[2 * sub + 1];
#pragma unroll
            for (int w = 0; w < 4; w++) {
                const uint32_t ua = (&a0.x)[w], ub = (&b0.x)[w];
                const float2 fa = bf2f(ua), fb = bf2f(ub);
                const float dx = fa.x - fb.x + EPSL, dy = fa.y - fb.y + EPSL;
                s += dx * dx + dy * dy;
            }
#pragma unroll
            for (int w = 0; w < 4; w++) {
                const uint32_t ua = (&a1.x)[w], ub = (&b1.x)[w];
                const float2 fa = bf2f(ua), fb = bf2f(ub);
                const float dx = fa.x - fb.x + EPSL, dy = fa.y - fb.y + EPSL;
                s += dx * dx + dy * dy;
            }
        }
        s += __shfl_xor_sync(0xffffffffu, s, 1);
        s += __shfl_xor_sync(0xffffffffu, s, 2);
        s += __shfl_xor_sync(0xffffffffu, s, 4);
        if (valid && sub == 0)
            local += beta_ps[e0] + beta_p[e1] - sqrt_approx(s);
    }
    // local is nonzero only on sub==0 lanes; full-warp reduce
#pragma unroll
    for (int o = 16; o; o >>= 1) local += __shfl_xor_sync(0xffffffffu, local, o);
    if (lane == 0) wsum[wid] = local;
    __syncthreads();
    if (threadIdx.x == 0) {
        float s = 0.f;
#pragma unroll
        for (int w = 0; w < 8; w++) s += wsum[w];
        atomicAdd(&g_acc[0], (double)s);
    }
}

// Non-link: persistent mma.sync bf16 GEMM over triu 128x128 tiles + fused epilogue.
// Single-stage smem (69.6 KB) -> 2 CTAs/SM for cross-CTA MMA/epilogue overlap.
// 8 warps per CTA, each a 32x64 strip.
__global__ __launch_bounds__(256, 2)
void k_nonlink_mma() {
    extern __shared__ __align__(16) char smem[];
    __shared__ float warpsum[8];
    const int tid  = threadIdx.x;
    const int wid  = tid >> 5;
    const int lane = tid & 31;
    const uint32_t sbase = smem_u32(smem);

    const int row0w = (wid & 3) * 32;     // 4 M-strips of 32
    const int col0w = (wid >> 2) * 64;    // 2 N-strips of 64

    float nls = 0.f;
    const uint32_t lm_off = (uint32_t)(lane & 15) * ROWB + (uint32_t)(lane >> 4) * 16;
    const uint32_t abase = sbase;
    const uint32_t bbase = sbase + TILEB;

    for (int t = blockIdx.x; t < NTILES; t += GRID_NL) {
        const uint32_t tc = g_tile[t];
        const int by = (int)(tc >> 16), bx = (int)(tc & 0xffffu);
        const int row0 = by << 7, col0 = bx << 7;

        // fill A (ps rows) + B (pp rows): 2048 16B chunks each, 256 threads
#pragma unroll
        for (int it = 0; it < 8; it++) {
            const int c = tid + (it << 8);
            const int m = c >> 4, q = c & 15;
            cp_async16(abase + (uint32_t)m * ROWB + (uint32_t)q * 16,
                       (const char*)g_ps_bf + ((size_t)(row0 + m) << 8) + ((size_t)q << 4));
            cp_async16(bbase + (uint32_t)m * ROWB + (uint32_t)q * 16,
                       (const char*)g_pp_bf + ((size_t)(col0 + m) << 8) + ((size_t)q << 4));
        }
        cp_commit();
        cp_wait<0>();
        __syncthreads();

        const uint32_t aw = abase + (uint32_t)row0w * ROWB + lm_off;
        const uint32_t bw = bbase + (uint32_t)col0w * ROWB + lm_off;

        float acc[2][8][4];
#pragma unroll
        for (int mi = 0; mi < 2; mi++)
#pragma unroll
            for (int ni = 0; ni < 8; ni++)
#pragma unroll
                for (int v = 0; v < 4; v++) acc[mi][ni][v] = 0.f;

#pragma unroll
        for (int k = 0; k < 8; k++) {
            uint32_t a[2][4], bf[4][4];
#pragma unroll
            for (int mi = 0; mi < 2; mi++)
                ldsm_x4(a[mi][0], a[mi][1], a[mi][2], a[mi][3],
                        aw + (uint32_t)mi * 16 * ROWB + (uint32_t)k * 32);
#pragma unroll
            for (int nj = 0; nj < 4; nj++)
                ldsm_x4(bf[nj][0], bf[nj][1], bf[nj][2], bf[nj][3],
                        bw + (uint32_t)nj * 16 * ROWB + (uint32_t)k * 32);
#pragma unroll
            for (int mi = 0; mi < 2; mi++)
#pragma unroll
                for (int ni = 0; ni < 8; ni++) {
                    const int nj = ni >> 1;
                    if ((ni & 1) == 0) mma16816(acc[mi][ni], a[mi], bf[nj][0], bf[nj][2]);
                    else               mma16816(acc[mi][ni], a[mi], bf[nj][1], bf[nj][3]);
                }
        }

        // fused epilogue (pre-scaled by L2E): w = ex2(bsum - sqrt(nsum - 2g))
        const int rbase = row0 + row0w + (lane >> 2);
        const int cbase = col0 + col0w + 2 * (lane & 3);
        if (bx != by) {
#pragma unroll
            for (int mi = 0; mi < 2; mi++) {
                const int r_lo = rbase + mi * 16;
                const float ns0 = __ldg(&g_ns[r_lo]),     bs0 = __ldg(&g_bs[r_lo]);
                const float ns1 = __ldg(&g_ns[r_lo + 8]), bs1 = __ldg(&g_bs[r_lo + 8]);
#pragma unroll
                for (int ni = 0; ni < 8; ni++) {
                    const int c0 = cbase + ni * 8;
                    const float np0 = __ldg(&g_np[c0]),     bp0 = __ldg(&g_bp[c0]);
                    const float np1 = __ldg(&g_np[c0 + 1]), bp1 = __ldg(&g_bp[c0 + 1]);
                    const float* d = acc[mi][ni];
                    nls += ex2_approx(bs0 + bp0 - sqrt_approx(fmaxf(ns0 + np0 - 2.f * d[0], 0.f)));
                    nls += ex2_approx(bs0 + bp1 - sqrt_approx(fmaxf(ns0 + np1 - 2.f * d[1], 0.f)));
                    nls += ex2_approx(bs1 + bp0 - sqrt_approx(fmaxf(ns1 + np0 - 2.f * d[2], 0.f)));
                    nls += ex2_approx(bs1 + bp1 - sqrt_approx(fmaxf(ns1 + np1 - 2.f * d[3], 0.f)));
                }
            }
        } else {
#pragma unroll
            for (int mi = 0; mi < 2; mi++) {
                const int r_lo = rbase + mi * 16;
                const float ns0 = __ldg(&g_ns[r_lo]),     bs0 = __ldg(&g_bs[r_lo]);
                const float ns1 = __ldg(&g_ns[r_lo + 8]), bs1 = __ldg(&g_bs[r_lo + 8]);
#pragma unroll
                for (int ni = 0; ni < 8; ni++) {
                    const int c0 = cbase + ni * 8;
                    const float np0 = __ldg(&g_np[c0]),     bp0 = __ldg(&g_bp[c0]);
                    const float np1 = __ldg(&g_np[c0 + 1]), bp1 = __ldg(&g_bp[c0 + 1]);
                    const float* d = acc[mi][ni];
                    float w;
                    w = ex2_approx(bs0 + bp0 - sqrt_approx(fmaxf(ns0 + np0 - 2.f * d[0], 0.f)));
                    if (r_lo < c0) nls += w;
                    w = ex2_approx(bs0 + bp1 - sqrt_approx(fmaxf(ns0 + np1 - 2.f * d[1], 0.f)));
                    if (r_lo < c0 + 1) nls += w;
                    w = ex2_approx(bs1 + bp0 - sqrt_approx(fmaxf(ns1 + np0 - 2.f * d[2], 0.f)));
                    if (r_lo + 8 < c0) nls += w;
                    w = ex2_approx(bs1 + bp1 - sqrt_approx(fmaxf(ns1 + np1 - 2.f * d[3], 0.f)));
                    if (r_lo + 8 < c0 + 1) nls += w;
                }
            }
        }
        __syncthreads();   // all warps done reading smem before next fill
    }

#pragma unroll
    for (int o = 16; o; o >>= 1) nls += __shfl_xor_sync(0xffffffffu, nls, o);
    if (lane == 0) warpsum[wid] = nls;
    __syncthreads();
    if (tid == 0) {
        float sum = 0.f;
#pragma unroll
        for (int w = 0; w < 8; w++) sum += warpsum[w];
        atomicAdd(&g_acc[1], (double)sum);
    }
}

__global__ void k_final(float* out) {
    out[0] = (float)(g_acc[1] - g_acc[0]);   // -(link - nonlink)
}

extern "C" void kernel_launch(void* const* d_in, const int* in_sizes, int n_in,
                              void* d_out, int out_size) {
    const int*   edges   = (const int*)d_in[0];
    const int*   nps     = (const int*)d_in[1];   // nodes_p_star
    const int*   npp     = (const int*)d_in[2];   // nodes_p
    const float* beta_p  = (const float*)d_in[3];
    const float* beta_ps = (const float*)d_in[4];
    const float* p       = (const float*)d_in[5];
    const float* pstar   = (const float*)d_in[6];
    float* out = (float*)d_out;
    int E = in_sizes[0] / 2;

    cudaFuncSetAttribute(k_nonlink_mma, cudaFuncAttributeMaxDynamicSharedMemorySize, DYN_SMEM_NL);

    k_init<<<(NTILES + 255) / 256, 256>>>();
    k_prep<<<(2 * NN + 7) / 8, 256>>>(p, pstar);
    k_gather<<<NB / 8, 256>>>(nps, npp, beta_p, beta_ps);
    k_link<<<2048, 256>>>(edges, E, beta_p, beta_ps);
    k_nonlink_mma<<<GRID_NL, 256, DYN_SMEM_NL>>>();
    k_final<<<1, 1>>>(out);
}

// round 6
// speedup vs baseline: 5.1420x; 1.0727x over previous
#include <cuda_runtime.h>
#include <cuda_bf16.h>
#include <cstdint>

#define DIMN 128
#define NB   16384
#define NN   20000
#define NT   (NB / 128)                 // 128 tile rows/cols
#define NTILES (NT * (NT + 1) / 2)      // 8256 triu tiles
#define EPSL 1e-6f
#define L2E  1.4426950408889634f
#define GRID_NL 296                     // 2 CTAs per SM
#define CHUNK ((NTILES + GRID_NL - 1) / GRID_NL)   // 28 tiles per CTA

// smem tile geometry: 128 rows x 128 bf16, padded to 136 bf16 (272 B) per row
#define ROWB 272
#define TILEB (128 * ROWB)              // 34816 B per operand tile
#define DYN_SMEM_NL (3 * TILEB)         // A + 2 stages of B = 104448 B

// ---- scratch (static device globals; no allocation) ----
__device__ __align__(16) __nv_bfloat16 g_p_bf[NN * DIMN];     // full p table, bf16
__device__ __align__(16) __nv_bfloat16 g_pstar_bf[NN * DIMN]; // full p_star table, bf16
__device__ __align__(16) __nv_bfloat16 g_ps_bf[NB * DIMN];    // L2E * p_star[nodes_p_star]
__device__ __align__(16) __nv_bfloat16 g_pp_bf[NB * DIMN];    // L2E * p[nodes_p]
__device__ float    g_ns[NB];          // |scaled ps row|^2
__device__ float    g_np[NB];          // |scaled pp row|^2
__device__ float    g_bs[NB];          // L2E * beta_p_star[nodes_p_star]
__device__ float    g_bp[NB];          // L2E * beta_p[nodes_p]
__device__ double   g_acc[2];          // [0]=link, [1]=nonlink

static __device__ __forceinline__ float sqrt_approx(float x) {
    float r; asm("sqrt.approx.f32 %0, %1;" : "=f"(r) : "f"(x)); return r;
}
static __device__ __forceinline__ float ex2_approx(float x) {
    float r; asm("ex2.approx.f32 %0, %1;" : "=f"(r) : "f"(x)); return r;
}
static __device__ __forceinline__ uint32_t smem_u32(const void* p) {
    uint32_t a;
    asm("{ .reg .u64 t; cvta.to.shared.u64 t, %1; cvt.u32.u64 %0, t; }" : "=r"(a) : "l"(p));
    return a;
}
static __device__ __forceinline__ void cp_async16(uint32_t dst, const void* src) {
    asm volatile("cp.async.cg.shared.global [%0], [%1], 16;" :: "r"(dst), "l"(src) : "memory");
}
static __device__ __forceinline__ void cp_commit() {
    asm volatile("cp.async.commit_group;" ::: "memory");
}
template <int N> static __device__ __forceinline__ void cp_wait() {
    asm volatile("cp.async.wait_group %0;" :: "n"(N) : "memory");
}
static __device__ __forceinline__ void ldsm_x4(uint32_t& r0, uint32_t& r1,
                                               uint32_t& r2, uint32_t& r3, uint32_t a) {
    asm volatile("ldmatrix.sync.aligned.m8n8.x4.shared.b16 {%0,%1,%2,%3}, [%4];"
                 : "=r"(r0), "=r"(r1), "=r"(r2), "=r"(r3) : "r"(a));
}
static __device__ __forceinline__ void mma16816(float* d, const uint32_t* a,
                                                uint32_t b0, uint32_t b1) {
    asm volatile("mma.sync.aligned.m16n8k16.row.col.f32.bf16.bf16.f32 "
                 "{%0,%1,%2,%3}, {%4,%5,%6,%7}, {%8,%9}, {%0,%1,%2,%3};"
                 : "+f"(d[0]), "+f"(d[1]), "+f"(d[2]), "+f"(d[3])
                 : "r"(a[0]), "r"(a[1]), "r"(a[2]), "r"(a[3]), "r"(b0), "r"(b1));
}
static __device__ __forceinline__ float2 bf2f(uint32_t u) {
    __nv_bfloat162 h = *reinterpret_cast<__nv_bfloat162*>(&u);
    return __bfloat1622float2(h);
}

// ---------------- kernels ----------------
// convert full p / p_star tables to bf16 (one warp per row per table); zero accumulators
__global__ void k_prep(const float* __restrict__ p, const float* __restrict__ pstar) {
    if (blockIdx.x == 0 && threadIdx.x == 0) { g_acc[0] = 0.0; g_acc[1] = 0.0; }
    int w    = blockIdx.x * 8 + (threadIdx.x >> 5);
    int lane = threadIdx.x & 31;
    int row  = w >> 1;
    if (row >= NN) return;
    const float* src = (w & 1) ? pstar : p;
    __nv_bfloat16* dst = (w & 1) ? g_pstar_bf : g_p_bf;
    float4 v = ((const float4*)(src + (size_t)row * DIMN))[lane];
    __nv_bfloat162* d = (__nv_bfloat162*)(dst + (size_t)row * DIMN);
    d[2 * lane + 0] = __floats2bfloat162_rn(v.x, v.y);
    d[2 * lane + 1] = __floats2bfloat162_rn(v.z, v.w);
}

// gather rows (from bf16 tables), scale by L2E, store scaled bf16 + norms + scaled betas
__global__ void k_gather(const int* __restrict__ nps, const int* __restrict__ npp,
                         const float* __restrict__ beta_p, const float* __restrict__ beta_ps) {
    int row  = blockIdx.x * 8 + (threadIdx.x >> 5);
    int lane = threadIdx.x & 31;
    if (row >= NB) return;
    int is = nps[row], ip = npp[row];
    uint2 rs = ((const uint2*)(g_pstar_bf + (size_t)is * DIMN))[lane];
    uint2 rp = ((const uint2*)(g_p_bf     + (size_t)ip * DIMN))[lane];

    float2 s0 = bf2f(rs.x), s1 = bf2f(rs.y), p0 = bf2f(rp.x), p1 = bf2f(rp.y);
    __nv_bfloat162 os0 = __floats2bfloat162_rn(s0.x * L2E, s0.y * L2E);
    __nv_bfloat162 os1 = __floats2bfloat162_rn(s1.x * L2E, s1.y * L2E);
    __nv_bfloat162 op0 = __floats2bfloat162_rn(p0.x * L2E, p0.y * L2E);
    __nv_bfloat162 op1 = __floats2bfloat162_rn(p1.x * L2E, p1.y * L2E);
    ((__nv_bfloat162*)(g_ps_bf + (size_t)row * DIMN))[2 * lane + 0] = os0;
    ((__nv_bfloat162*)(g_ps_bf + (size_t)row * DIMN))[2 * lane + 1] = os1;
    ((__nv_bfloat162*)(g_pp_bf + (size_t)row * DIMN))[2 * lane + 0] = op0;
    ((__nv_bfloat162*)(g_pp_bf + (size_t)row * DIMN))[2 * lane + 1] = op1;

    float2 a0 = __bfloat1622float2(os0), a1 = __bfloat1622float2(os1);
    float2 b0 = __bfloat1622float2(op0), b1 = __bfloat1622float2(op1);
    float a = a0.x*a0.x + a0.y*a0.y + a1.x*a1.x + a1.y*a1.y;
    float b = b0.x*b0.x + b0.y*b0.y + b1.x*b1.x + b1.y*b1.y;
#pragma unroll
    for (int o = 16; o; o >>= 1) {
        a += __shfl_xor_sync(0xffffffffu, a, o);
        b += __shfl_xor_sync(0xffffffffu, b, o);
    }
    if (lane == 0) {
        g_ns[row] = a; g_np[row] = b;
        g_bs[row] = beta_ps[is] * L2E; g_bp[row] = beta_p[ip] * L2E;
    }
}

// Link term: 8 lanes per edge, 4 edges per warp in parallel (3-deep shfl reduce).
__global__ void k_link(const int* __restrict__ edges, int E,
                       const float* __restrict__ beta_p, const float* __restrict__ beta_ps) {
    __shared__ float wsum[8];
    const int gw   = (blockIdx.x * blockDim.x + threadIdx.x) >> 5;
    const int wid  = threadIdx.x >> 5;
    const int lane = threadIdx.x & 31;
    const int nw   = (gridDim.x * blockDim.x) >> 5;
    const int sub  = lane & 7;
    const int eq   = lane >> 3;

    float local = 0.f;
    for (int base = gw * 4; base < E; base += nw * 4) {
        const int e = base + eq;
        const bool valid = (e < E);
        float s = 0.f;
        int e0 = 0, e1 = 0;
        if (valid) {
            e0 = edges[e]; e1 = edges[E + e];
            const uint4* ra = (const uint4*)(g_p_bf     + (size_t)e0 * DIMN);
            const uint4* rb = (const uint4*)(g_pstar_bf + (size_t)e1 * DIMN);
            const uint4 a0 = ra[2 * sub], a1 = ra[2 * sub + 1];
            const uint4 b0 = rb[2 * sub], b1 = rb[2 * sub + 1];
#pragma unroll
            for (int w = 0; w < 4; w++) {
                const float2 fa = bf2f((&a0.x)[w]), fb = bf2f((&b0.x)[w]);
                const float dx = fa.x - fb.x + EPSL, dy = fa.y - fb.y + EPSL;
                s += dx * dx + dy * dy;
            }
#pragma unroll
            for (int w = 0; w < 4; w++) {
                const float2 fa = bf2f((&a1.x)[w]), fb = bf2f((&b1.x)[w]);
                const float dx = fa.x - fb.x + EPSL, dy = fa.y - fb.y + EPSL;
                s += dx * dx + dy * dy;
            }
        }
        s += __shfl_xor_sync(0xffffffffu, s, 1);
        s += __shfl_xor_sync(0xffffffffu, s, 2);
        s += __shfl_xor_sync(0xffffffffu, s, 4);
        if (valid && sub == 0)
            local += beta_ps[e0] + beta_p[e1] - sqrt_approx(s);
    }
#pragma unroll
    for (int o = 16; o; o >>= 1) local += __shfl_xor_sync(0xffffffffu, local, o);
    if (lane == 0) wsum[wid] = local;
    __syncthreads();
    if (threadIdx.x == 0) {
        float s = 0.f;
#pragma unroll
        for (int w = 0; w < 8; w++) s += wsum[w];
        atomicAdd(&g_acc[0], (double)s);
    }
}

// Non-link: persistent mma.sync bf16 GEMM. Each CTA owns CHUNK contiguous row-major
// triu tiles: A (ps rows) persists across same-row tiles; B double-buffered cp.async.
// smem = A + 2*B = 104.4 KB -> 2 CTAs/SM. 8 warps, 32x64 strip each.
__global__ __launch_bounds__(256, 2)
void k_nonlink_mma() {
    extern __shared__ __align__(16) char smem[];
    __shared__ float warpsum[8];
    const int tid  = threadIdx.x;
    const int wid  = tid >> 5;
    const int lane = tid & 31;
    const uint32_t sbase = smem_u32(smem);
    const uint32_t abase = sbase;                 // A tile
    const uint32_t bst[2] = { sbase + TILEB, sbase + 2 * TILEB };

    const int row0w = (wid & 3) * 32;
    const int col0w = (wid >> 2) * 64;
    const uint32_t lm_off = (uint32_t)(lane & 15) * ROWB + (uint32_t)(lane >> 4) * 16;

    float nls = 0.f;

    const int t0 = blockIdx.x * CHUNK;
    const int t1 = (t0 + CHUNK < NTILES) ? (t0 + CHUNK) : NTILES;

    if (t0 < NTILES) {
        // decode t0 -> (by, bx) by row scan (<=128 iterations, once per CTA)
        int by = 0, rem = t0;
        while (rem >= NT - by) { rem -= NT - by; by++; }
        int bx = by + rem;

        // prologue: A(by) + B(bx) into stage 0, one cp.async group
#pragma unroll
        for (int it = 0; it < 8; it++) {
            const int c = tid + (it << 8);
            const int m = c >> 4, q = c & 15;
            cp_async16(abase + (uint32_t)m * ROWB + (uint32_t)q * 16,
                       (const char*)g_ps_bf + ((size_t)((by << 7) + m) << 8) + ((size_t)q << 4));
            cp_async16(bst[0] + (uint32_t)m * ROWB + (uint32_t)q * 16,
                       (const char*)g_pp_bf + ((size_t)((bx << 7) + m) << 8) + ((size_t)q << 4));
        }
        cp_commit();

        int s = 0;
        for (int t = t0; t < t1; t++) {
            // next tile coords (row-major triu increment)
            int nbx = bx + 1, nby = by;
            if (nbx >= NT) { nby = by + 1; nbx = nby; }
            const bool have_next = (t + 1 < t1);

            // prefetch next B into other stage
            if (have_next) {
#pragma unroll
                for (int it = 0; it < 8; it++) {
                    const int c = tid + (it << 8);
                    const int m = c >> 4, q = c & 15;
                    cp_async16(bst[1 - s] + (uint32_t)m * ROWB + (uint32_t)q * 16,
                               (const char*)g_pp_bf + ((size_t)((nbx << 7) + m) << 8) + ((size_t)q << 4));
                }
            }
            cp_commit();
            cp_wait<1>();       // current B (+ any pending A refill) resident
            __syncthreads();

            const int row0 = by << 7, col0 = bx << 7;
            const uint32_t aw = abase  + (uint32_t)row0w * ROWB + lm_off;
            const uint32_t bw = bst[s] + (uint32_t)col0w * ROWB + lm_off;

            float acc[2][8][4];
#pragma unroll
            for (int mi = 0; mi < 2; mi++)
#pragma unroll
                for (int ni = 0; ni < 8; ni++)
#pragma unroll
                    for (int v = 0; v < 4; v++) acc[mi][ni][v] = 0.f;

#pragma unroll
            for (int k = 0; k < 8; k++) {
                uint32_t a[2][4], bf[4][4];
#pragma unroll
                for (int mi = 0; mi < 2; mi++)
                    ldsm_x4(a[mi][0], a[mi][1], a[mi][2], a[mi][3],
                            aw + (uint32_t)mi * 16 * ROWB + (uint32_t)k * 32);
#pragma unroll
                for (int nj = 0; nj < 4; nj++)
                    ldsm_x4(bf[nj][0], bf[nj][1], bf[nj][2], bf[nj][3],
                            bw + (uint32_t)nj * 16 * ROWB + (uint32_t)k * 32);
#pragma unroll
                for (int mi = 0; mi < 2; mi++)
#pragma unroll
                    for (int ni = 0; ni < 8; ni++) {
                        const int nj = ni >> 1;
                        if ((ni & 1) == 0) mma16816(acc[mi][ni], a[mi], bf[nj][0], bf[nj][2]);
                        else               mma16816(acc[mi][ni], a[mi], bf[nj][1], bf[nj][3]);
                    }
            }

            // fused epilogue (values pre-scaled by L2E): w = ex2(bsum - sqrt(nsum - 2g))
            const int rbase = row0 + row0w + (lane >> 2);
            const int cbase = col0 + col0w + 2 * (lane & 3);
            if (bx != by) {
#pragma unroll
                for (int mi = 0; mi < 2; mi++) {
                    const int r_lo = rbase + mi * 16;
                    const float ns0 = __ldg(&g_ns[r_lo]),     bs0 = __ldg(&g_bs[r_lo]);
                    const float ns1 = __ldg(&g_ns[r_lo + 8]), bs1 = __ldg(&g_bs[r_lo + 8]);
#pragma unroll
                    for (int ni = 0; ni < 8; ni++) {
                        const int c0 = cbase + ni * 8;
                        const float np0 = __ldg(&g_np[c0]),     bp0 = __ldg(&g_bp[c0]);
                        const float np1 = __ldg(&g_np[c0 + 1]), bp1 = __ldg(&g_bp[c0 + 1]);
                        const float* d = acc[mi][ni];
                        nls += ex2_approx(bs0 + bp0 - sqrt_approx(fmaxf(ns0 + np0 - 2.f * d[0], 0.f)));
                        nls += ex2_approx(bs0 + bp1 - sqrt_approx(fmaxf(ns0 + np1 - 2.f * d[1], 0.f)));
                        nls += ex2_approx(bs1 + bp0 - sqrt_approx(fmaxf(ns1 + np0 - 2.f * d[2], 0.f)));
                        nls += ex2_approx(bs1 + bp1 - sqrt_approx(fmaxf(ns1 + np1 - 2.f * d[3], 0.f)));
                    }
                }
            } else {
#pragma unroll
                for (int mi = 0; mi < 2; mi++) {
                    const int r_lo = rbase + mi * 16;
                    const float ns0 = __ldg(&g_ns[r_lo]),     bs0 = __ldg(&g_bs[r_lo]);
                    const float ns1 = __ldg(&g_ns[r_lo + 8]), bs1 = __ldg(&g_bs[r_lo + 8]);
#pragma unroll
                    for (int ni = 0; ni < 8; ni++) {
                        const int c0 = cbase + ni * 8;
                        const float np0 = __ldg(&g_np[c0]),     bp0 = __ldg(&g_bp[c0]);
                        const float np1 = __ldg(&g_np[c0 + 1]), bp1 = __ldg(&g_bp[c0 + 1]);
                        const float* d = acc[mi][ni];
                        float w;
                        w = ex2_approx(bs0 + bp0 - sqrt_approx(fmaxf(ns0 + np0 - 2.f * d[0], 0.f)));
                        if (r_lo < c0) nls += w;
                        w = ex2_approx(bs0 + bp1 - sqrt_approx(fmaxf(ns0 + np1 - 2.f * d[1], 0.f)));
                        if (r_lo < c0 + 1) nls += w;
                        w = ex2_approx(bs1 + bp0 - sqrt_approx(fmaxf(ns1 + np0 - 2.f * d[2], 0.f)));
                        if (r_lo + 8 < c0) nls += w;
                        w = ex2_approx(bs1 + bp1 - sqrt_approx(fmaxf(ns1 + np1 - 2.f * d[3], 0.f)));
                        if (r_lo + 8 < c0 + 1) nls += w;
                    }
                }
            }
            __syncthreads();   // everyone done with A + B stage s

            // A refill for next tile's row (rare; rides behind the B prefetch group)
            if (have_next && nby != by) {
#pragma unroll
                for (int it = 0; it < 8; it++) {
                    const int c = tid + (it << 8);
                    const int m = c >> 4, q = c & 15;
                    cp_async16(abase + (uint32_t)m * ROWB + (uint32_t)q * 16,
                               (const char*)g_ps_bf + ((size_t)((nby << 7) + m) << 8) + ((size_t)q << 4));
                }
                cp_commit();
            }
            by = nby; bx = nbx; s ^= 1;
        }
    }

#pragma unroll
    for (int o = 16; o; o >>= 1) nls += __shfl_xor_sync(0xffffffffu, nls, o);
    if (lane == 0) warpsum[wid] = nls;
    __syncthreads();
    if (tid == 0) {
        float sum = 0.f;
#pragma unroll
        for (int w = 0; w < 8; w++) sum += warpsum[w];
        atomicAdd(&g_acc[1], (double)sum);
    }
}

__global__ void k_final(float* out) {
    out[0] = (float)(g_acc[1] - g_acc[0]);   // -(link - nonlink)
}

extern "C" void kernel_launch(void* const* d_in, const int* in_sizes, int n_in,
                              void* d_out, int out_size) {
    const int*   edges   = (const int*)d_in[0];
    const int*   nps     = (const int*)d_in[1];   // nodes_p_star
    const int*   npp     = (const int*)d_in[2];   // nodes_p
    const float* beta_p  = (const float*)d_in[3];
    const float* beta_ps = (const float*)d_in[4];
    const float* p       = (const float*)d_in[5];
    const float* pstar   = (const float*)d_in[6];
    float* out = (float*)d_out;
    int E = in_sizes[0] / 2;

    cudaFuncSetAttribute(k_nonlink_mma, cudaFuncAttributeMaxDynamicSharedMemorySize, DYN_SMEM_NL);

    k_prep<<<(2 * NN + 7) / 8, 256>>>(p, pstar);
    k_gather<<<NB / 8, 256>>>(nps, npp, beta_p, beta_ps);
    k_link<<<2048, 256>>>(edges, E, beta_p, beta_ps);
    k_nonlink_mma<<<GRID_NL, 256, DYN_SMEM_NL>>>();
    k_final<<<1, 1>>>(out);
}